// round 4
// baseline (speedup 1.0000x reference)
#include <cuda_runtime.h>
#include <cuda_bf16.h>
#include <math.h>

#define NN 50000
#define EE 800000
#define FIN 256
#define HD 64
#define CC 10
#define GG 64
#define NB_SCAN 196   // ceil(NN/256)

// ---------------- device scratch (no allocation allowed) ----------------
__device__ int   g_cnt[NN];        // in-degree histogram
__device__ int   g_fill[NN];       // CSR fill cursors
__device__ int   g_rowstart[NN];   // CSR row starts (exclusive scan of cnt)
__device__ int   g_scan[NN];       // per-block inclusive scan scratch
__device__ int   g_blk[256];       // block totals
__device__ int   g_blkoff[256];    // block offsets (exclusive)
__device__ float g_dis[NN];        // deg^{-1/2}
__device__ int2  g_csr[EE];        // CSR: (src, weight-bits) packed
__device__ float g_bufH[NN * HD];  // GEMM output h = x @ W
__device__ float g_bufA[NN * HD];  // activation (input of next layer)
__device__ int   g_gstart[GG + 1]; // graph segment starts (batch sorted)
__device__ int   g_is64;           // 1 if edge_index/batch are int64

// ---------------- index accessor (int32 vs int64) ----------------
__device__ __forceinline__ long long get_idx(const void* p, long long i, int is64) {
    if (is64) return ((const long long*)p)[i];
    return (long long)((const int*)p)[i];
}

// ---------------- dtype detection ----------------
__global__ void k_detect(const int* __restrict__ words) {
    __shared__ int red[256];
    int tid = threadIdx.x;
    int acc = 0;
    for (int j = 0; j < 32; j++) {
        long long w = 1 + 2LL * (tid + 256LL * j * 97);
        if (w < 2LL * EE) acc |= words[w];
    }
    red[tid] = acc;
    __syncthreads();
    for (int s = 128; s > 0; s >>= 1) {
        if (tid < s) red[tid] |= red[tid + s];
        __syncthreads();
    }
    if (tid == 0) g_is64 = (red[0] == 0) ? 1 : 0;
}

// ---------------- CSR build ----------------
__global__ void k_zero_cf() {
    int i = blockIdx.x * blockDim.x + threadIdx.x;
    if (i < NN) { g_cnt[i] = 0; g_fill[i] = 0; }
}

__global__ void k_hist(const void* __restrict__ ei) {
    int e = blockIdx.x * blockDim.x + threadIdx.x;
    if (e >= EE) return;
    int d = (int)get_idx(ei, (long long)EE + e, g_is64);
    atomicAdd(&g_cnt[d], 1);
}

__global__ void k_dis_k() {
    int i = blockIdx.x * blockDim.x + threadIdx.x;
    if (i < NN) g_dis[i] = rsqrtf((float)g_cnt[i] + 1.0f);
}

__global__ void k_scanA() {
    __shared__ int sh[256];
    int t = threadIdx.x;
    int i = blockIdx.x * 256 + t;
    int v = (i < NN) ? g_cnt[i] : 0;
    sh[t] = v;
    __syncthreads();
    #pragma unroll
    for (int off = 1; off < 256; off <<= 1) {
        int add = (t >= off) ? sh[t - off] : 0;
        __syncthreads();
        sh[t] += add;
        __syncthreads();
    }
    if (i < NN) g_scan[i] = sh[t];
    if (t == 255) g_blk[blockIdx.x] = sh[255];
}

__global__ void k_scanB() {
    __shared__ int sh[256];
    int t = threadIdx.x;
    int v = (t < NB_SCAN) ? g_blk[t] : 0;
    sh[t] = v;
    __syncthreads();
    #pragma unroll
    for (int off = 1; off < 256; off <<= 1) {
        int add = (t >= off) ? sh[t - off] : 0;
        __syncthreads();
        sh[t] += add;
        __syncthreads();
    }
    g_blkoff[t] = sh[t] - v;   // exclusive
}

__global__ void k_scanC_fix() {
    int i = blockIdx.x * 256 + threadIdx.x;
    if (i < NN) g_rowstart[i] = g_scan[i] - g_cnt[i] + g_blkoff[blockIdx.x];
}

__global__ void k_fill(const void* __restrict__ ei) {
    int e = blockIdx.x * blockDim.x + threadIdx.x;
    if (e >= EE) return;
    int is64 = g_is64;
    int s = (int)get_idx(ei, e, is64);
    int d = (int)get_idx(ei, (long long)EE + e, is64);
    int pos = g_rowstart[d] + atomicAdd(&g_fill[d], 1);
    float w = g_dis[s] * g_dis[d];
    g_csr[pos] = make_int2(s, __float_as_int(w));
}

// ---------------- tiled fp32 GEMM, 128x64 block tile, 8x4 per thread ------
// Out[M x 64] = A[M x K] @ W[K x 64]. K-tile = 32.
// As stored with row stride 33: broadcast reads As[row*33+kk] hit distinct
// banks across the 8 rows of a thread; A-tile scalar stores are conflict-free.
template<int K>
__global__ void __launch_bounds__(256, 2) k_gemm(const float* __restrict__ A,
                                                 const float* __restrict__ W,
                                                 float* __restrict__ Out, int M) {
    __shared__ float As[128 * 33];   // 16.9 KB
    __shared__ float Ws[32 * 68];    // 8.7 KB
    int tid = threadIdx.x;
    int tx  = tid & 15;              // col quad: cols tx*4..tx*4+3
    int ty  = tid >> 4;              // row octet: rows ty*8..ty*8+7
    int r0  = blockIdx.x * 128;
    unsigned long long acc[8][2] = {};   // packed (f32,f32) accumulators

    for (int kt = 0; kt < K; kt += 32) {
        // load A tile: 128 rows x 32 k
        #pragma unroll
        for (int j = 0; j < 4; j++) {
            int s   = tid + j * 256;
            int row = s >> 3;
            int cv  = s & 7;
            float4 v = make_float4(0.f, 0.f, 0.f, 0.f);
            int gr = r0 + row;
            if (gr < M) v = *(const float4*)&A[(size_t)gr * K + kt + cv * 4];
            float* p = &As[row * 33 + cv * 4];
            p[0] = v.x; p[1] = v.y; p[2] = v.z; p[3] = v.w;
        }
        // load W tile: 32 k-rows x 64 cols
        #pragma unroll
        for (int j = 0; j < 2; j++) {
            int s  = tid + j * 256;
            int wr = s >> 4;
            int wc = s & 15;
            *(float4*)&Ws[wr * 68 + wc * 4] = *(const float4*)&W[(size_t)(kt + wr) * 64 + wc * 4];
        }
        __syncthreads();
        #pragma unroll 4
        for (int kk = 0; kk < 32; kk++) {
            float4 b = *(const float4*)&Ws[kk * 68 + tx * 4];
            unsigned long long b01, b23;
            asm("mov.b64 %0, {%1, %2};" : "=l"(b01) : "f"(b.x), "f"(b.y));
            asm("mov.b64 %0, {%1, %2};" : "=l"(b23) : "f"(b.z), "f"(b.w));
            #pragma unroll
            for (int i = 0; i < 8; i++) {
                float a = As[(ty * 8 + i) * 33 + kk];
                unsigned long long aa;
                asm("mov.b64 %0, {%1, %1};" : "=l"(aa) : "f"(a));
                asm("fma.rn.f32x2 %0, %1, %2, %0;" : "+l"(acc[i][0]) : "l"(aa), "l"(b01));
                asm("fma.rn.f32x2 %0, %1, %2, %0;" : "+l"(acc[i][1]) : "l"(aa), "l"(b23));
            }
        }
        __syncthreads();
    }
    #pragma unroll
    for (int i = 0; i < 8; i++) {
        int gr = r0 + ty * 8 + i;
        if (gr < M) {
            float4 v;
            asm("mov.b64 {%0, %1}, %2;" : "=f"(v.x), "=f"(v.y) : "l"(acc[i][0]));
            asm("mov.b64 {%0, %1}, %2;" : "=f"(v.z), "=f"(v.w) : "l"(acc[i][1]));
            *(float4*)&Out[(size_t)gr * 64 + tx * 4] = v;
        }
    }
}

// ---------------- CSR gather (warp per node, 2 features/lane, unroll 4) ----
__global__ void k_gather(const float* __restrict__ bias) {
    int warp = (blockIdx.x * blockDim.x + threadIdx.x) >> 5;
    int lane = threadIdx.x & 31;
    if (warp >= NN) return;
    int n    = warp;
    int beg  = g_rowstart[n];
    int cnt  = g_cnt[n];
    int end  = beg + cnt;
    const float2* __restrict__ H = (const float2*)g_bufH;

    float ax = 0.0f, ay = 0.0f;
    int e = beg;
    int end4 = beg + (cnt & ~3);
    for (; e < end4; e += 4) {
        int2 p0 = g_csr[e + 0];
        int2 p1 = g_csr[e + 1];
        int2 p2 = g_csr[e + 2];
        int2 p3 = g_csr[e + 3];
        float w0 = __int_as_float(p0.y);
        float w1 = __int_as_float(p1.y);
        float w2 = __int_as_float(p2.y);
        float w3 = __int_as_float(p3.y);
        float2 v0 = H[(size_t)p0.x * 32 + lane];
        float2 v1 = H[(size_t)p1.x * 32 + lane];
        float2 v2 = H[(size_t)p2.x * 32 + lane];
        float2 v3 = H[(size_t)p3.x * 32 + lane];
        ax += v0.x * w0 + v1.x * w1 + v2.x * w2 + v3.x * w3;
        ay += v0.y * w0 + v1.y * w1 + v2.y * w2 + v3.y * w3;
    }
    for (; e < end; e++) {
        int2 p0 = g_csr[e];
        float w0 = __int_as_float(p0.y);
        float2 v0 = H[(size_t)p0.x * 32 + lane];
        ax += v0.x * w0;
        ay += v0.y * w0;
    }
    // self loop
    float dn = g_dis[n];
    float sn = dn * dn;
    float2 hv = H[(size_t)n * 32 + lane];
    ax += hv.x * sn;
    ay += hv.y * sn;
    // bias + relu
    ax = fmaxf(ax + bias[2 * lane], 0.0f);
    ay = fmaxf(ay + bias[2 * lane + 1], 0.0f);
    ((float2*)g_bufA)[(size_t)n * 32 + lane] = make_float2(ax, ay);
}

// ---------------- pooling via sorted-batch segments ----------------
__global__ void k_bounds(const void* __restrict__ batch) {
    int g = threadIdx.x;
    if (g > GG) return;
    int is64 = g_is64;
    int lo = 0, hi = NN;
    while (lo < hi) {
        int mid = (lo + hi) >> 1;
        long long v = get_idx(batch, mid, is64);
        if (v < (long long)g) lo = mid + 1; else hi = mid;
    }
    g_gstart[g] = lo;
}

__global__ void k_poolfinal(const float* __restrict__ linW,
                            const float* __restrict__ linb,
                            float* __restrict__ out) {
    __shared__ float sp[4][64];
    int t = threadIdx.x;
    int f = t & 63;
    int r = t >> 6;           // 0..3
    int g = blockIdx.x;
    int s = g_gstart[g], eN = g_gstart[g + 1];
    float acc = 0.0f;
    for (int n = s + r; n < eN; n += 4)
        acc += g_bufA[(size_t)n * 64 + f];
    sp[r][f] = acc;
    __syncthreads();
    if (t < 64) {
        float total = sp[0][t] + sp[1][t] + sp[2][t] + sp[3][t];
        float cntf = (float)(eN - s);
        sp[0][t] = total / fmaxf(cntf, 1.0f);
    }
    __syncthreads();
    if (t < CC) {
        float o = linb[t];
        #pragma unroll 16
        for (int h = 0; h < HD; h++)
            o += sp[0][h] * linW[h * CC + t];
        out[g * CC + t] = o;
    }
}

// ---------------- host launcher (graph-capturable) ----------------
extern "C" void kernel_launch(void* const* d_in, const int* in_sizes, int n_in,
                              void* d_out, int out_size) {
    const float* x    = (const float*)d_in[0];
    const void*  ei   = d_in[1];
    const void*  bat  = d_in[2];
    const float* W1   = (const float*)d_in[3];
    const float* b1   = (const float*)d_in[4];
    const float* W2   = (const float*)d_in[5];
    const float* b2   = (const float*)d_in[6];
    const float* W3   = (const float*)d_in[7];
    const float* b3   = (const float*)d_in[8];
    const float* linW = (const float*)d_in[9];
    const float* linb = (const float*)d_in[10];
    float* out = (float*)d_out;

    const int T = 256;
    int nbN    = (NN + T - 1) / T;            // 196
    int nbE    = (EE + T - 1) / T;            // 3125
    int nbGemm = (NN + 127) / 128;            // 391
    int nbGath = (NN * 32 + T - 1) / T;       // one warp per node

    static float* pH = nullptr; static float* pA = nullptr;
    if (!pH) {
        void* tmp;
        cudaGetSymbolAddress(&tmp, g_bufH); pH = (float*)tmp;
        cudaGetSymbolAddress(&tmp, g_bufA); pA = (float*)tmp;
    }

    // preprocessing; GEMM1 stays in profiled launch slot (index 3)
    k_detect<<<1, 256>>>((const int*)ei);          // 0
    k_zero_cf<<<nbN, T>>>();                       // 1
    k_hist<<<nbE, T>>>(ei);                        // 2
    k_gemm<FIN><<<nbGemm, T>>>(x, W1, pH, NN);     // 3  <- ncu profiles this
    k_dis_k<<<nbN, T>>>();                         // 4
    k_scanA<<<NB_SCAN, 256>>>();
    k_scanB<<<1, 256>>>();
    k_scanC_fix<<<NB_SCAN, 256>>>();
    k_fill<<<nbE, T>>>(ei);

    // ---- layer 1 (gemm already issued above) ----
    k_gather<<<nbGath, T>>>(b1);

    // ---- layer 2 ----
    k_gemm<HD><<<nbGemm, T>>>(pA, W2, pH, NN);
    k_gather<<<nbGath, T>>>(b2);

    // ---- layer 3 ----
    k_gemm<HD><<<nbGemm, T>>>(pA, W3, pH, NN);
    k_gather<<<nbGath, T>>>(b3);

    // ---- pool + classify (sorted batch -> segment sums, no atomics) ----
    k_bounds<<<1, GG + 1>>>(bat);
    k_poolfinal<<<GG, 256>>>(linW, linb, out);
}

// round 6
// speedup vs baseline: 1.0959x; 1.0959x over previous
#include <cuda_runtime.h>
#include <cuda_bf16.h>
#include <math.h>
#include <stdint.h>

#define NN 50000
#define EE 800000
#define FIN 256
#define HD 64
#define CC 10
#define GG 64
#define NB_SCAN 196   // ceil(NN/256)

// ---------------- device scratch (no allocation allowed) ----------------
__device__ int   g_cnt[NN];        // in-degree histogram
__device__ int   g_fill[NN];       // CSR fill cursors
__device__ int   g_rowstart[NN];   // CSR row starts (exclusive scan of cnt)
__device__ int   g_scan[NN];       // per-block inclusive scan scratch
__device__ int   g_blk[256];       // block totals
__device__ int   g_blkoff[256];    // block offsets (exclusive)
__device__ float g_dis[NN];        // deg^{-1/2}
__device__ int2  g_csr[EE];        // CSR: (src, weight-bits) packed
__device__ __nv_bfloat16 g_bufHb[NN * HD]; // h as bf16 (128B per node row)
__device__ float g_bufA[NN * HD];  // activation fp32 (input of next GEMM)
__device__ int   g_gstart[GG + 1]; // graph segment starts (batch sorted)
__device__ int   g_is64;           // 1 if edge_index/batch are int64

// ---------------- index accessor (int32 vs int64) ----------------
__device__ __forceinline__ long long get_idx(const void* p, long long i, int is64) {
    if (is64) return ((const long long*)p)[i];
    return (long long)((const int*)p)[i];
}

// ---------------- dtype detection ----------------
__global__ void k_detect(const int* __restrict__ words) {
    __shared__ int red[256];
    int tid = threadIdx.x;
    int acc = 0;
    for (int j = 0; j < 32; j++) {
        long long w = 1 + 2LL * (tid + 256LL * j * 97);
        if (w < 2LL * EE) acc |= words[w];
    }
    red[tid] = acc;
    __syncthreads();
    for (int s = 128; s > 0; s >>= 1) {
        if (tid < s) red[tid] |= red[tid + s];
        __syncthreads();
    }
    if (tid == 0) g_is64 = (red[0] == 0) ? 1 : 0;
}

// ---------------- CSR build ----------------
__global__ void k_zero_cf() {
    int i = blockIdx.x * blockDim.x + threadIdx.x;
    if (i < NN) { g_cnt[i] = 0; g_fill[i] = 0; }
}

__global__ void k_hist(const void* __restrict__ ei) {
    int e = blockIdx.x * blockDim.x + threadIdx.x;
    if (e >= EE) return;
    int d = (int)get_idx(ei, (long long)EE + e, g_is64);
    atomicAdd(&g_cnt[d], 1);
}

__global__ void k_dis_k() {
    int i = blockIdx.x * blockDim.x + threadIdx.x;
    if (i < NN) g_dis[i] = rsqrtf((float)g_cnt[i] + 1.0f);
}

__global__ void k_scanA() {
    __shared__ int sh[256];
    int t = threadIdx.x;
    int i = blockIdx.x * 256 + t;
    int v = (i < NN) ? g_cnt[i] : 0;
    sh[t] = v;
    __syncthreads();
    #pragma unroll
    for (int off = 1; off < 256; off <<= 1) {
        int add = (t >= off) ? sh[t - off] : 0;
        __syncthreads();
        sh[t] += add;
        __syncthreads();
    }
    if (i < NN) g_scan[i] = sh[t];
    if (t == 255) g_blk[blockIdx.x] = sh[255];
}

__global__ void k_scanB() {
    __shared__ int sh[256];
    int t = threadIdx.x;
    int v = (t < NB_SCAN) ? g_blk[t] : 0;
    sh[t] = v;
    __syncthreads();
    #pragma unroll
    for (int off = 1; off < 256; off <<= 1) {
        int add = (t >= off) ? sh[t - off] : 0;
        __syncthreads();
        sh[t] += add;
        __syncthreads();
    }
    g_blkoff[t] = sh[t] - v;   // exclusive
}

__global__ void k_scanC_fix() {
    int i = blockIdx.x * 256 + threadIdx.x;
    if (i < NN) g_rowstart[i] = g_scan[i] - g_cnt[i] + g_blkoff[blockIdx.x];
}

__global__ void k_fill(const void* __restrict__ ei) {
    int e = blockIdx.x * blockDim.x + threadIdx.x;
    if (e >= EE) return;
    int is64 = g_is64;
    int s = (int)get_idx(ei, e, is64);
    int d = (int)get_idx(ei, (long long)EE + e, is64);
    int pos = g_rowstart[d] + atomicAdd(&g_fill[d], 1);
    float w = g_dis[s] * g_dis[d];
    g_csr[pos] = make_int2(s, __float_as_int(w));
}

// ---------------- tiled fp32 GEMM, 64x64 tile, 4x4/thread, bf16 output -----
// Hout[M x 64](bf16) = A[M x K](fp32) @ W[K x 64](fp32)
template<int K>
__global__ void k_gemm(const float* __restrict__ A, const float* __restrict__ W,
                       __nv_bfloat16* __restrict__ Out, int M) {
    __shared__ float As[64][68];
    __shared__ float Ws[64][64];
    int tid = threadIdx.x;
    int r0  = blockIdx.x * 64;
    int tx  = tid & 15;       // output col quad
    int ty  = tid >> 4;       // output row quad
    unsigned long long acc[4][2] = {};   // packed (f32,f32) pairs

    for (int kt = 0; kt < K; kt += 64) {
        #pragma unroll
        for (int j = 0; j < 4; j++) {
            int s   = tid + j * 256;
            int row = s >> 4;
            int cv  = s & 15;
            float4 v = make_float4(0.f, 0.f, 0.f, 0.f);
            int gr = r0 + row;
            if (gr < M) v = *(const float4*)&A[(size_t)gr * K + kt + cv * 4];
            *(float4*)&As[row][cv * 4] = v;
        }
        #pragma unroll
        for (int j = 0; j < 4; j++) {
            int s   = tid + j * 256;
            int row = s >> 4;
            int cv  = s & 15;
            *(float4*)&Ws[row][cv * 4] = *(const float4*)&W[(size_t)(kt + row) * 64 + cv * 4];
        }
        __syncthreads();
        #pragma unroll 16
        for (int kk = 0; kk < 64; kk++) {
            float4 b = *(const float4*)&Ws[kk][tx * 4];
            unsigned long long b01, b23;
            asm("mov.b64 %0, {%1, %2};" : "=l"(b01) : "f"(b.x), "f"(b.y));
            asm("mov.b64 %0, {%1, %2};" : "=l"(b23) : "f"(b.z), "f"(b.w));
            #pragma unroll
            for (int i = 0; i < 4; i++) {
                float a = As[ty * 4 + i][kk];
                unsigned long long aa;
                asm("mov.b64 %0, {%1, %1};" : "=l"(aa) : "f"(a));
                asm("fma.rn.f32x2 %0, %1, %2, %0;" : "+l"(acc[i][0]) : "l"(aa), "l"(b01));
                asm("fma.rn.f32x2 %0, %1, %2, %0;" : "+l"(acc[i][1]) : "l"(aa), "l"(b23));
            }
        }
        __syncthreads();
    }
    #pragma unroll
    for (int i = 0; i < 4; i++) {
        int gr = r0 + ty * 4 + i;
        if (gr < M) {
            float2 lo, hi;
            asm("mov.b64 {%0, %1}, %2;" : "=f"(lo.x), "=f"(lo.y) : "l"(acc[i][0]));
            asm("mov.b64 {%0, %1}, %2;" : "=f"(hi.x), "=f"(hi.y) : "l"(acc[i][1]));
            __nv_bfloat162 p0 = __float22bfloat162_rn(lo);
            __nv_bfloat162 p1 = __float22bfloat162_rn(hi);
            uint2 st;
            st.x = *(uint32_t*)&p0;
            st.y = *(uint32_t*)&p1;
            *(uint2*)&Out[(size_t)gr * 64 + tx * 4] = st;
        }
    }
}

// ---------------- CSR gather (warp/node, bf16 features, fp32 accumulate) ----
// One warp per dst node; each lane owns 2 features (one bf16x2 = 4B load).
__global__ void k_gather(const float* __restrict__ bias) {
    int warp = (blockIdx.x * blockDim.x + threadIdx.x) >> 5;
    int lane = threadIdx.x & 31;
    if (warp >= NN) return;
    int n   = warp;
    int beg = g_rowstart[n];
    int cnt = g_cnt[n];
    int end = beg + cnt;
    const __nv_bfloat162* __restrict__ H = (const __nv_bfloat162*)g_bufHb;

    float ax = 0.0f, ay = 0.0f;
    int e = beg;
    int end4 = beg + (cnt & ~3);
    for (; e < end4; e += 4) {
        int2 p0 = g_csr[e + 0];
        int2 p1 = g_csr[e + 1];
        int2 p2 = g_csr[e + 2];
        int2 p3 = g_csr[e + 3];
        float2 v0 = __bfloat1622float2(H[(size_t)p0.x * 32 + lane]);
        float2 v1 = __bfloat1622float2(H[(size_t)p1.x * 32 + lane]);
        float2 v2 = __bfloat1622float2(H[(size_t)p2.x * 32 + lane]);
        float2 v3 = __bfloat1622float2(H[(size_t)p3.x * 32 + lane]);
        float w0 = __int_as_float(p0.y);
        float w1 = __int_as_float(p1.y);
        float w2 = __int_as_float(p2.y);
        float w3 = __int_as_float(p3.y);
        ax += v0.x * w0 + v1.x * w1 + v2.x * w2 + v3.x * w3;
        ay += v0.y * w0 + v1.y * w1 + v2.y * w2 + v3.y * w3;
    }
    for (; e < end; e++) {
        int2 p0 = g_csr[e];
        float2 v0 = __bfloat1622float2(H[(size_t)p0.x * 32 + lane]);
        float w0 = __int_as_float(p0.y);
        ax += v0.x * w0;
        ay += v0.y * w0;
    }
    // self loop
    float dn = g_dis[n];
    float sn = dn * dn;
    float2 hv = __bfloat1622float2(H[(size_t)n * 32 + lane]);
    ax += hv.x * sn;
    ay += hv.y * sn;
    // bias + relu -> fp32 activation (input of next GEMM / pooling)
    ax = fmaxf(ax + bias[2 * lane], 0.0f);
    ay = fmaxf(ay + bias[2 * lane + 1], 0.0f);
    ((float2*)g_bufA)[(size_t)n * 32 + lane] = make_float2(ax, ay);
}

// ---------------- pooling via sorted-batch segments ----------------
__global__ void k_bounds(const void* __restrict__ batch) {
    int g = threadIdx.x;
    if (g > GG) return;
    int is64 = g_is64;
    int lo = 0, hi = NN;
    while (lo < hi) {
        int mid = (lo + hi) >> 1;
        long long v = get_idx(batch, mid, is64);
        if (v < (long long)g) lo = mid + 1; else hi = mid;
    }
    g_gstart[g] = lo;
}

__global__ void k_poolfinal(const float* __restrict__ linW,
                            const float* __restrict__ linb,
                            float* __restrict__ out) {
    __shared__ float sp[4][64];
    int t = threadIdx.x;
    int f = t & 63;
    int r = t >> 6;           // 0..3
    int g = blockIdx.x;
    int s = g_gstart[g], eN = g_gstart[g + 1];
    float acc = 0.0f;
    for (int n = s + r; n < eN; n += 4)
        acc += g_bufA[(size_t)n * 64 + f];
    sp[r][f] = acc;
    __syncthreads();
    if (t < 64) {
        float total = sp[0][t] + sp[1][t] + sp[2][t] + sp[3][t];
        float cntf = (float)(eN - s);
        sp[0][t] = total / fmaxf(cntf, 1.0f);
    }
    __syncthreads();
    if (t < CC) {
        float o = linb[t];
        #pragma unroll 16
        for (int h = 0; h < HD; h++)
            o += sp[0][h] * linW[h * CC + t];
        out[g * CC + t] = o;
    }
}

// ---------------- host launcher (graph-capturable) ----------------
extern "C" void kernel_launch(void* const* d_in, const int* in_sizes, int n_in,
                              void* d_out, int out_size) {
    const float* x    = (const float*)d_in[0];
    const void*  ei   = d_in[1];
    const void*  bat  = d_in[2];
    const float* W1   = (const float*)d_in[3];
    const float* b1   = (const float*)d_in[4];
    const float* W2   = (const float*)d_in[5];
    const float* b2   = (const float*)d_in[6];
    const float* W3   = (const float*)d_in[7];
    const float* b3   = (const float*)d_in[8];
    const float* linW = (const float*)d_in[9];
    const float* linb = (const float*)d_in[10];
    float* out = (float*)d_out;

    const int T = 256;
    int nbN    = (NN + T - 1) / T;           // 196
    int nbE    = (EE + T - 1) / T;           // 3125
    int nbGemm = (NN + 63) / 64;             // 782
    int nbGath = (NN * 32 + T - 1) / T;      // one warp per node

    static __nv_bfloat16* pH = nullptr;
    static float* pA = nullptr;
    if (!pH) {
        void* tmp;
        cudaGetSymbolAddress(&tmp, g_bufHb); pH = (__nv_bfloat16*)tmp;
        cudaGetSymbolAddress(&tmp, g_bufA);  pA = (float*)tmp;
    }

    // preprocessing; GEMM1 stays in profiled launch slot (index 3)
    k_detect<<<1, 256>>>((const int*)ei);          // 0
    k_zero_cf<<<nbN, T>>>();                       // 1
    k_hist<<<nbE, T>>>(ei);                        // 2
    k_gemm<FIN><<<nbGemm, T>>>(x, W1, pH, NN);     // 3  <- ncu profiles this
    k_dis_k<<<nbN, T>>>();                         // 4
    k_scanA<<<NB_SCAN, 256>>>();
    k_scanB<<<1, 256>>>();
    k_scanC_fix<<<NB_SCAN, 256>>>();
    k_fill<<<nbE, T>>>(ei);

    // ---- layer 1 (gemm already issued above) ----
    k_gather<<<nbGath, T>>>(b1);

    // ---- layer 2 ----
    k_gemm<HD><<<nbGemm, T>>>(pA, W2, pH, NN);
    k_gather<<<nbGath, T>>>(b2);

    // ---- layer 3 ----
    k_gemm<HD><<<nbGemm, T>>>(pA, W3, pH, NN);
    k_gather<<<nbGath, T>>>(b3);

    // ---- pool + classify (sorted batch -> segment sums, no atomics) ----
    k_bounds<<<1, GG + 1>>>(bat);
    k_poolfinal<<<GG, 256>>>(linW, linb, out);
}